// round 11
// baseline (speedup 1.0000x reference)
#include <cuda_runtime.h>
#include <stdint.h>

// ======================= device globals (scratch; no allocs) =======================
// Statically zero-initialized; dq_config resets counters after reading them, so
// every graph replay starts from the same state (no init kernel needed).
__device__ unsigned int g_over_cnt  = 0u;
__device__ unsigned int g_under_cnt = 0u;
__device__ float4       g_qparams;   // {sigma, 1/sigma, t_min, t_max}
__device__ int          g_fix;       // 1 if speculation (sigma=0.125) was wrong

// ======================= threefry2x32 (20 rounds, Random123/JAX) ===================
// mul-based rotate: x<<r = mul.lo(x,2^r), x>>(32-r) = mul.hi(x,2^r); both on the
// fma pipe. The caller's (lo|hi)^x0 fuses into a single LOP3 on the alu pipe.
// 4 of the 20 rounds use this form to balance alu vs issue floors
// (model: alu = 2*(41-k), issue = 72+k  ->  k ~= 4 equalizes at ~76 cyc).
__device__ __forceinline__ uint32_t rotl_mul(uint32_t x, uint32_t pow)
{
    uint32_t lo, hi;
    asm("mul.lo.u32 %0, %1, %2;" : "=r"(lo) : "r"(x), "r"(pow));
    asm("mul.hi.u32 %0, %1, %2;" : "=r"(hi) : "r"(x), "r"(pow));
    return lo | hi;
}

// Counter = (0, ctr); returns o0 ^ o1 (JAX partitionable 32-bit bits).
__device__ __forceinline__ uint32_t tf_bits32(
    uint32_t x1,               // caller passes ctr + k1
    uint32_t k0, uint32_t k1, uint32_t k2,
    uint32_t k2p1, uint32_t k0p2, uint32_t k1p3, uint32_t k2p4, uint32_t k0p5)
{
#define TF_R(r)  { x0 += x1; x1 = __funnelshift_l(x1, x1, (r)); x1 ^= x0; }
#define TF_RM(r) { x0 += x1; x1 = rotl_mul(x1, 1u << (r)) ^ x0; }
    // rounds 1-4 (x0 starts at k0)
    uint32_t x0 = k0 + x1;
    x1 = __funnelshift_l(x1, x1, 13) ^ x0;
    TF_R(15) TF_RM(26) TF_R(6)            // round 3: mul-rotate
    // inject (k1, k2+1), rounds 5-8
    x1 += k2p1; x0 = x0 + x1 + k1;
    x1 = __funnelshift_l(x1, x1, 17) ^ x0;
    TF_R(29) TF_R(16) TF_RM(24)           // round 8: mul-rotate
    // inject (k2, k0+2), rounds 9-12
    x1 += k0p2; x0 = x0 + x1 + k2;
    x1 = __funnelshift_l(x1, x1, 13) ^ x0;
    TF_R(15) TF_RM(26) TF_R(6)            // round 11: mul-rotate
    // inject (k0, k1+3), rounds 13-16
    x1 += k1p3; x0 = x0 + x1 + k0;
    x1 = __funnelshift_l(x1, x1, 17) ^ x0;
    TF_R(29) TF_R(16) TF_RM(24)           // round 16: mul-rotate
    // inject (k1, k2+4), rounds 17-20
    x1 += k2p4; x0 = x0 + x1 + k1;
    x1 = __funnelshift_l(x1, x1, 13) ^ x0;
    TF_R(15) TF_R(26) TF_R(6)
    // final injection (k2, k0+5) folded into the output xor's operands
    return (x0 + k2) ^ (x1 + k0p5);
#undef TF_R
#undef TF_RM
}

// JAX uniform in [0,1): (float)(bits>>9) * 2^-23, bit-exact vs bitcast-or-sub-1.
// bits>>9 via umulhi (fma pipe) instead of SHF (alu pipe).
__device__ __forceinline__ float tf_uniform(uint32_t bits)
{
    return (float)__umulhi(bits, 1u << 23) * 0x1p-23f;
}

// floor + clamp-to-[-128,127] in one conversion op, then scale.
// Exact: clip(floor(t)*s, -128s, 127s) == clamp(floor(t),-128,127)*s for s=2^-k.
__device__ __forceinline__ float dq_floor_sat_scale(float t, float sigma)
{
    int s8;
    asm("cvt.rmi.sat.s8.f32 %0, %1;" : "=r"(s8) : "f"(t));
    float f;
    asm("cvt.rn.f32.s8 %0, %1;" : "=f"(f) : "r"(s8));
    return f * sigma;
}

// Exact shifted-abs overflow/underflow tests (sigma0 = 0.25):
//   over : v>31.75  || v<-32  <=> |v+0.125 | > 31.875
//   under: v>15.875 || v<-16  <=> |v+0.0625| > 15.9375
__device__ __forceinline__ void dq_count_exact(float v, unsigned& over, unsigned& under)
{
    over  += (unsigned)(fabsf(v + 0.125f)  > 31.875f);
    under += (unsigned)(fabsf(v + 0.0625f) > 15.9375f);
}

// ======================= kernels ===================================================

// Fused: speculative quantize (sigma=0.125) + conservative count test.
// 8 elements per thread: two coalesced float4 groups at i and i+n8.
// Fast-path test: the under condition (8v>127 || 8v<-128) implies |t|>127 where
// t = fma(v,8,r), r in [0,1). Exact counts run only in the warp-converged rare path.
__global__ void __launch_bounds__(256) dq_main(
    const float4* __restrict__ x, float4* __restrict__ out, unsigned n8,
    uint32_t k0, uint32_t k1, uint32_t k2,
    uint32_t k2p1, uint32_t k0p2, uint32_t k1p3, uint32_t k2p4, uint32_t k0p5)
{
    unsigned i = blockIdx.x * blockDim.x + threadIdx.x;
    bool maybe = false;
    bool active = (i < n8);
    float4 va, vb;

    if (active) {
        unsigned j = i + n8;
        va = x[i];
        vb = x[j];
        // chain counters: ctr+k1 = IMAD(i,4,k1)+m
        uint32_t ca = i * 4u + k1;
        uint32_t cb = j * 4u + k1;

        uint32_t b0 = tf_bits32(ca + 0u, k0, k1, k2, k2p1, k0p2, k1p3, k2p4, k0p5);
        uint32_t b1 = tf_bits32(ca + 1u, k0, k1, k2, k2p1, k0p2, k1p3, k2p4, k0p5);
        uint32_t b2 = tf_bits32(ca + 2u, k0, k1, k2, k2p1, k0p2, k1p3, k2p4, k0p5);
        uint32_t b3 = tf_bits32(ca + 3u, k0, k1, k2, k2p1, k0p2, k1p3, k2p4, k0p5);
        uint32_t b4 = tf_bits32(cb + 0u, k0, k1, k2, k2p1, k0p2, k1p3, k2p4, k0p5);
        uint32_t b5 = tf_bits32(cb + 1u, k0, k1, k2, k2p1, k0p2, k1p3, k2p4, k0p5);
        uint32_t b6 = tf_bits32(cb + 2u, k0, k1, k2, k2p1, k0p2, k1p3, k2p4, k0p5);
        uint32_t b7 = tf_bits32(cb + 3u, k0, k1, k2, k2p1, k0p2, k1p3, k2p4, k0p5);

        float t0 = fmaf(va.x, 8.0f, tf_uniform(b0));
        float t1 = fmaf(va.y, 8.0f, tf_uniform(b1));
        float t2 = fmaf(va.z, 8.0f, tf_uniform(b2));
        float t3 = fmaf(va.w, 8.0f, tf_uniform(b3));
        float t4 = fmaf(vb.x, 8.0f, tf_uniform(b4));
        float t5 = fmaf(vb.y, 8.0f, tf_uniform(b5));
        float t6 = fmaf(vb.z, 8.0f, tf_uniform(b6));
        float t7 = fmaf(vb.w, 8.0f, tf_uniform(b7));

        float4 qa, qb;
        qa.x = dq_floor_sat_scale(t0, 0.125f);
        qa.y = dq_floor_sat_scale(t1, 0.125f);
        qa.z = dq_floor_sat_scale(t2, 0.125f);
        qa.w = dq_floor_sat_scale(t3, 0.125f);
        qb.x = dq_floor_sat_scale(t4, 0.125f);
        qb.y = dq_floor_sat_scale(t5, 0.125f);
        qb.z = dq_floor_sat_scale(t6, 0.125f);
        qb.w = dq_floor_sat_scale(t7, 0.125f);
        out[i] = qa;
        out[j] = qb;

        // conservative fast test (superset of the under condition) over all 8
        float m = fmaxf(fmaxf(fmaxf(fabsf(t0), fabsf(t1)), fmaxf(fabsf(t2), fabsf(t3))),
                        fmaxf(fmaxf(fabsf(t4), fabsf(t5)), fmaxf(fabsf(t6), fabsf(t7))));
        maybe = (m > 127.0f);
    }

    // single warp-converged vote; inactive threads vote false
    if (__any_sync(0xffffffffu, maybe)) {
        unsigned over = 0u, under = 0u;
        if (active) {
            dq_count_exact(va.x, over, under);
            dq_count_exact(va.y, over, under);
            dq_count_exact(va.z, over, under);
            dq_count_exact(va.w, over, under);
            dq_count_exact(vb.x, over, under);
            dq_count_exact(vb.y, over, under);
            dq_count_exact(vb.z, over, under);
            dq_count_exact(vb.w, over, under);
        }
#pragma unroll
        for (int o = 16; o > 0; o >>= 1) {
            over  += __shfl_down_sync(0xffffffffu, over,  o);
            under += __shfl_down_sync(0xffffffffu, under, o);
        }
        if ((threadIdx.x & 31) == 0 && (over | under)) {
            atomicAdd(&g_over_cnt,  over);
            atomicAdd(&g_under_cnt, under);
        }
    }
}

// Scalar tail: exact count + speculative quant for elements [start, n).
__global__ void dq_tail(const float* __restrict__ x, float* __restrict__ out,
                        int start, int n,
                        uint32_t k0, uint32_t k1, uint32_t k2,
                        uint32_t k2p1, uint32_t k0p2, uint32_t k1p3,
                        uint32_t k2p4, uint32_t k0p5)
{
    unsigned over = 0u, under = 0u;
    for (int i = start; i < n; i++) {
        float v = x[i];
        dq_count_exact(v, over, under);
        uint32_t b = tf_bits32((uint32_t)i + k1, k0, k1, k2,
                               k2p1, k0p2, k1p3, k2p4, k0p5);
        float t = fmaf(v, 8.0f, tf_uniform(b));
        out[i] = dq_floor_sat_scale(t, 0.125f);
    }
    if (over)  atomicAdd(&g_over_cnt,  over);
    if (under) atomicAdd(&g_under_cnt, under);
}

// Decision (mirrors reference float32 math) + counter reset for replay determinism.
__global__ void dq_config(float nf)
{
    float overf  = (float)g_over_cnt  / nf;
    float underf = (float)g_under_cnt / nf;
    float sigma, inv;
    if (overf > 0.01f)        { sigma = 0.5f;   inv = 2.0f; }
    else if (underf < 0.01f)  { sigma = 0.125f; inv = 8.0f; }
    else                      { sigma = 0.25f;  inv = 4.0f; }
    g_qparams = make_float4(sigma, inv, -sigma * 128.0f, sigma * 127.0f);
    g_fix = (sigma != 0.125f) ? 1 : 0;
    g_over_cnt  = 0u;     // self-clean: next replay starts from zero
    g_under_cnt = 0u;
}

// Conditional fixup: re-quantize with the chosen sigma iff speculation was wrong.
// The s8 saturation range [-128,127] is the clip range for every sigma choice.
__global__ void __launch_bounds__(256) dq_fixup(
    const float* __restrict__ x, float* __restrict__ out, int n,
    uint32_t k0, uint32_t k1, uint32_t k2,
    uint32_t k2p1, uint32_t k0p2, uint32_t k1p3, uint32_t k2p4, uint32_t k0p5)
{
    if (!g_fix) return;
    float4 p = g_qparams;
    const float sigma = p.x, inv = p.y;
    for (int i = blockIdx.x * blockDim.x + threadIdx.x; i < n;
         i += gridDim.x * blockDim.x) {
        uint32_t b = tf_bits32((uint32_t)i + k1, k0, k1, k2,
                               k2p1, k0p2, k1p3, k2p4, k0p5);
        float t = fmaf(x[i], inv, tf_uniform(b));
        out[i] = dq_floor_sat_scale(t, sigma);
    }
}

// ======================= host side =================================================
static inline uint32_t h_rotl(uint32_t v, int r) { return (v << r) | (v >> (32 - r)); }

static void host_threefry(uint32_t k0, uint32_t k1, uint32_t x0, uint32_t x1,
                          uint32_t* o0, uint32_t* o1)
{
    uint32_t k2 = k0 ^ k1 ^ 0x1BD11BDAu;
    x0 += k0; x1 += k1;
#define HR(r) { x0 += x1; x1 = h_rotl(x1, (r)); x1 ^= x0; }
    HR(13) HR(15) HR(26) HR(6)
    x0 += k1; x1 += k2 + 1u;
    HR(17) HR(29) HR(16) HR(24)
    x0 += k2; x1 += k0 + 2u;
    HR(13) HR(15) HR(26) HR(6)
    x0 += k0; x1 += k1 + 3u;
    HR(17) HR(29) HR(16) HR(24)
    x0 += k1; x1 += k2 + 4u;
    HR(13) HR(15) HR(26) HR(6)
    x0 += k2; x1 += k0 + 5u;
#undef HR
    *o0 = x0; *o1 = x1;
}

extern "C" void kernel_launch(void* const* d_in, const int* in_sizes, int n_in,
                              void* d_out, int out_size)
{
    const float* x   = (const float*)d_in[0];
    float*       out = (float*)d_out;
    const int n  = in_sizes[0];
    const int n4 = n >> 2;
    const int n8 = n4 >> 1;          // threads in main; covers 8*n8 elements
    const int covered = n8 << 3;

    // folded key: fold_in(key(42), 0) = threefry((0,42), (0,0))
    uint32_t fk0, fk1;
    host_threefry(0u, 42u, 0u, 0u, &fk0, &fk1);
    uint32_t fk2  = fk0 ^ fk1 ^ 0x1BD11BDAu;
    uint32_t k2p1 = fk2 + 1u;
    uint32_t k0p2 = fk0 + 2u;
    uint32_t k1p3 = fk1 + 3u;
    uint32_t k2p4 = fk2 + 4u;
    uint32_t k0p5 = fk0 + 5u;

    if (n8 > 0) {
        unsigned blocks = (unsigned)((n8 + 255) / 256);
        dq_main<<<blocks, 256>>>((const float4*)x, (float4*)out, (unsigned)n8,
                                 fk0, fk1, fk2, k2p1, k0p2, k1p3, k2p4, k0p5);
    }
    if (covered < n) {
        dq_tail<<<1, 1>>>(x, out, covered, n,
                          fk0, fk1, fk2, k2p1, k0p2, k1p3, k2p4, k0p5);
    }

    dq_config<<<1, 1>>>((float)n);

    dq_fixup<<<2048, 256>>>(x, out, n,
                            fk0, fk1, fk2, k2p1, k0p2, k1p3, k2p4, k0p5);
}

// round 14
// speedup vs baseline: 1.0064x; 1.0064x over previous
#include <cuda_runtime.h>
#include <stdint.h>

// ======================= device globals (scratch; no allocs) =======================
// Statically zero-initialized; dq_config resets counters after reading them, so
// every graph replay starts from the same state (no init kernel needed).
__device__ unsigned int g_over_cnt  = 0u;
__device__ unsigned int g_under_cnt = 0u;
__device__ float4       g_qparams;   // {sigma, 1/sigma, t_min, t_max}
__device__ int          g_fix;       // 1 if speculation (sigma=0.125) was wrong

// ======================= threefry2x32 (20 rounds, Random123/JAX) ===================
// R10 configuration (best measured): exactly one mul-rotate round, IADD3-fused
// key injections. mul-based rotate: x<<r = mul.lo(x,2^r), x>>(32-r) = mul.hi.
__device__ __forceinline__ uint32_t rotl_mul(uint32_t x, uint32_t pow)
{
    uint32_t lo, hi;
    asm("mul.lo.u32 %0, %1, %2;" : "=r"(lo) : "r"(x), "r"(pow));
    asm("mul.hi.u32 %0, %1, %2;" : "=r"(hi) : "r"(x), "r"(pow));
    return lo | hi;
}

// Counter = (0, ctr); returns o0 ^ o1 (JAX partitionable 32-bit bits).
__device__ __forceinline__ uint32_t tf_bits32(
    uint32_t x1,               // caller passes ctr + k1
    uint32_t k0, uint32_t k1, uint32_t k2,
    uint32_t k2p1, uint32_t k0p2, uint32_t k1p3, uint32_t k2p4, uint32_t k0p5)
{
#define TF_R(r)  { x0 += x1; x1 = __funnelshift_l(x1, x1, (r)); x1 ^= x0; }
#define TF_RM(r) { x0 += x1; x1 = rotl_mul(x1, 1u << (r)) ^ x0; }
    // rounds 1-4 (x0 starts at k0)
    uint32_t x0 = k0 + x1;
    x1 = __funnelshift_l(x1, x1, 13) ^ x0;
    TF_R(15) TF_RM(26) TF_R(6)            // round 3: mul-rotate
    // inject (k1, k2+1), rounds 5-8
    x1 += k2p1; x0 = x0 + x1 + k1;
    x1 = __funnelshift_l(x1, x1, 17) ^ x0;
    TF_R(29) TF_R(16) TF_R(24)
    // inject (k2, k0+2), rounds 9-12
    x1 += k0p2; x0 = x0 + x1 + k2;
    x1 = __funnelshift_l(x1, x1, 13) ^ x0;
    TF_R(15) TF_R(26) TF_R(6)
    // inject (k0, k1+3), rounds 13-16
    x1 += k1p3; x0 = x0 + x1 + k0;
    x1 = __funnelshift_l(x1, x1, 17) ^ x0;
    TF_R(29) TF_R(16) TF_R(24)
    // inject (k1, k2+4), rounds 17-20
    x1 += k2p4; x0 = x0 + x1 + k1;
    x1 = __funnelshift_l(x1, x1, 13) ^ x0;
    TF_R(15) TF_R(26) TF_R(6)
    // final injection (k2, k0+5) folded into the output xor's operands
    return (x0 + k2) ^ (x1 + k0p5);
#undef TF_R
#undef TF_RM
}

// JAX uniform in [0,1): (float)(bits>>9) * 2^-23, bit-exact vs bitcast-or-sub-1.
__device__ __forceinline__ float tf_uniform(uint32_t bits)
{
    return (float)__umulhi(bits, 1u << 23) * 0x1p-23f;
}

// floor + clamp-to-[-128,127] in one conversion op, then scale.
// Exact: clip(floor(t)*s, -128s, 127s) == clamp(floor(t),-128,127)*s for s=2^-k.
__device__ __forceinline__ float dq_floor_sat_scale(float t, float sigma)
{
    int s8;
    asm("cvt.rmi.sat.s8.f32 %0, %1;" : "=r"(s8) : "f"(t));
    float f;
    asm("cvt.rn.f32.s8 %0, %1;" : "=f"(f) : "r"(s8));
    return f * sigma;
}

// Exact shifted-abs overflow/underflow tests (sigma0 = 0.25):
//   over : v>31.75  || v<-32  <=> |v+0.125 | > 31.875
//   under: v>15.875 || v<-16  <=> |v+0.0625| > 15.9375
__device__ __forceinline__ void dq_count_exact(float v, unsigned& over, unsigned& under)
{
    over  += (unsigned)(fabsf(v + 0.125f)  > 31.875f);
    under += (unsigned)(fabsf(v + 0.0625f) > 15.9375f);
}

// ======================= kernels ===================================================

// Persistent fused kernel: one wave of CTAs; each thread grid-strides over
// float4-pair groups (8 elements per iteration at float4 indices i and i+n8).
// Speculative quantize (sigma=0.125) + deferred count: per iteration only the
// running max |t| is updated; the vote + exact counting runs ONCE per thread
// after the loop (rare path re-reads x; never taken when speculation holds).
// Fast-test soundness: the under condition (8v>127 || 8v<-128) implies |t|>127
// where t = fma(v,8,r), r in [0,1); over-condition implies it a fortiori.
__global__ void __launch_bounds__(256) dq_main(
    const float4* __restrict__ x, float4* __restrict__ out, unsigned n8,
    uint32_t k0, uint32_t k1, uint32_t k2,
    uint32_t k2p1, uint32_t k0p2, uint32_t k1p3, uint32_t k2p4, uint32_t k0p5)
{
    const unsigned tid0   = blockIdx.x * blockDim.x + threadIdx.x;
    const unsigned stride = gridDim.x * blockDim.x;

    float m_acc = 0.0f;

    for (unsigned i = tid0; i < n8; i += stride) {
        unsigned j = i + n8;
        float4 va = x[i];
        float4 vb = x[j];
        uint32_t ca = i * 4u + k1;      // ctr + k1
        uint32_t cb = j * 4u + k1;

        uint32_t b0 = tf_bits32(ca + 0u, k0, k1, k2, k2p1, k0p2, k1p3, k2p4, k0p5);
        uint32_t b1 = tf_bits32(ca + 1u, k0, k1, k2, k2p1, k0p2, k1p3, k2p4, k0p5);
        uint32_t b2 = tf_bits32(ca + 2u, k0, k1, k2, k2p1, k0p2, k1p3, k2p4, k0p5);
        uint32_t b3 = tf_bits32(ca + 3u, k0, k1, k2, k2p1, k0p2, k1p3, k2p4, k0p5);
        uint32_t b4 = tf_bits32(cb + 0u, k0, k1, k2, k2p1, k0p2, k1p3, k2p4, k0p5);
        uint32_t b5 = tf_bits32(cb + 1u, k0, k1, k2, k2p1, k0p2, k1p3, k2p4, k0p5);
        uint32_t b6 = tf_bits32(cb + 2u, k0, k1, k2, k2p1, k0p2, k1p3, k2p4, k0p5);
        uint32_t b7 = tf_bits32(cb + 3u, k0, k1, k2, k2p1, k0p2, k1p3, k2p4, k0p5);

        float t0 = fmaf(va.x, 8.0f, tf_uniform(b0));
        float t1 = fmaf(va.y, 8.0f, tf_uniform(b1));
        float t2 = fmaf(va.z, 8.0f, tf_uniform(b2));
        float t3 = fmaf(va.w, 8.0f, tf_uniform(b3));
        float t4 = fmaf(vb.x, 8.0f, tf_uniform(b4));
        float t5 = fmaf(vb.y, 8.0f, tf_uniform(b5));
        float t6 = fmaf(vb.z, 8.0f, tf_uniform(b6));
        float t7 = fmaf(vb.w, 8.0f, tf_uniform(b7));

        float4 qa, qb;
        qa.x = dq_floor_sat_scale(t0, 0.125f);
        qa.y = dq_floor_sat_scale(t1, 0.125f);
        qa.z = dq_floor_sat_scale(t2, 0.125f);
        qa.w = dq_floor_sat_scale(t3, 0.125f);
        qb.x = dq_floor_sat_scale(t4, 0.125f);
        qb.y = dq_floor_sat_scale(t5, 0.125f);
        qb.z = dq_floor_sat_scale(t6, 0.125f);
        qb.w = dq_floor_sat_scale(t7, 0.125f);
        out[i] = qa;
        out[j] = qb;

        // running conservative max over all elements this thread touched
        float m = fmaxf(fmaxf(fmaxf(fabsf(t0), fabsf(t1)), fmaxf(fabsf(t2), fabsf(t3))),
                        fmaxf(fmaxf(fabsf(t4), fabsf(t5)), fmaxf(fabsf(t6), fabsf(t7))));
        m_acc = fmaxf(m_acc, m);
    }

    // single warp-converged vote per thread (all threads exit the loop)
    if (__any_sync(0xffffffffu, m_acc > 127.0f)) {
        unsigned over = 0u, under = 0u;
        for (unsigned i = tid0; i < n8; i += stride) {
            float4 va = x[i];
            float4 vb = x[i + n8];
            dq_count_exact(va.x, over, under);
            dq_count_exact(va.y, over, under);
            dq_count_exact(va.z, over, under);
            dq_count_exact(va.w, over, under);
            dq_count_exact(vb.x, over, under);
            dq_count_exact(vb.y, over, under);
            dq_count_exact(vb.z, over, under);
            dq_count_exact(vb.w, over, under);
        }
#pragma unroll
        for (int o = 16; o > 0; o >>= 1) {
            over  += __shfl_down_sync(0xffffffffu, over,  o);
            under += __shfl_down_sync(0xffffffffu, under, o);
        }
        if ((threadIdx.x & 31) == 0 && (over | under)) {
            atomicAdd(&g_over_cnt,  over);
            atomicAdd(&g_under_cnt, under);
        }
    }
}

// Scalar tail: exact count + speculative quant for elements [start, n).
__global__ void dq_tail(const float* __restrict__ x, float* __restrict__ out,
                        int start, int n,
                        uint32_t k0, uint32_t k1, uint32_t k2,
                        uint32_t k2p1, uint32_t k0p2, uint32_t k1p3,
                        uint32_t k2p4, uint32_t k0p5)
{
    unsigned over = 0u, under = 0u;
    for (int i = start; i < n; i++) {
        float v = x[i];
        dq_count_exact(v, over, under);
        uint32_t b = tf_bits32((uint32_t)i + k1, k0, k1, k2,
                               k2p1, k0p2, k1p3, k2p4, k0p5);
        float t = fmaf(v, 8.0f, tf_uniform(b));
        out[i] = dq_floor_sat_scale(t, 0.125f);
    }
    if (over)  atomicAdd(&g_over_cnt,  over);
    if (under) atomicAdd(&g_under_cnt, under);
}

// Decision (mirrors reference float32 math) + counter reset for replay determinism.
__global__ void dq_config(float nf)
{
    float overf  = (float)g_over_cnt  / nf;
    float underf = (float)g_under_cnt / nf;
    float sigma, inv;
    if (overf > 0.01f)        { sigma = 0.5f;   inv = 2.0f; }
    else if (underf < 0.01f)  { sigma = 0.125f; inv = 8.0f; }
    else                      { sigma = 0.25f;  inv = 4.0f; }
    g_qparams = make_float4(sigma, inv, -sigma * 128.0f, sigma * 127.0f);
    g_fix = (sigma != 0.125f) ? 1 : 0;
    g_over_cnt  = 0u;     // self-clean: next replay starts from zero
    g_under_cnt = 0u;
}

// Conditional fixup: re-quantize with the chosen sigma iff speculation was wrong.
// The s8 saturation range [-128,127] is the clip range for every sigma choice.
__global__ void __launch_bounds__(256) dq_fixup(
    const float* __restrict__ x, float* __restrict__ out, int n,
    uint32_t k0, uint32_t k1, uint32_t k2,
    uint32_t k2p1, uint32_t k0p2, uint32_t k1p3, uint32_t k2p4, uint32_t k0p5)
{
    if (!g_fix) return;
    float4 p = g_qparams;
    const float sigma = p.x, inv = p.y;
    for (int i = blockIdx.x * blockDim.x + threadIdx.x; i < n;
         i += gridDim.x * blockDim.x) {
        uint32_t b = tf_bits32((uint32_t)i + k1, k0, k1, k2,
                               k2p1, k0p2, k1p3, k2p4, k0p5);
        float t = fmaf(x[i], inv, tf_uniform(b));
        out[i] = dq_floor_sat_scale(t, sigma);
    }
}

// ======================= host side =================================================
static inline uint32_t h_rotl(uint32_t v, int r) { return (v << r) | (v >> (32 - r)); }

static void host_threefry(uint32_t k0, uint32_t k1, uint32_t x0, uint32_t x1,
                          uint32_t* o0, uint32_t* o1)
{
    uint32_t k2 = k0 ^ k1 ^ 0x1BD11BDAu;
    x0 += k0; x1 += k1;
#define HR(r) { x0 += x1; x1 = h_rotl(x1, (r)); x1 ^= x0; }
    HR(13) HR(15) HR(26) HR(6)
    x0 += k1; x1 += k2 + 1u;
    HR(17) HR(29) HR(16) HR(24)
    x0 += k2; x1 += k0 + 2u;
    HR(13) HR(15) HR(26) HR(6)
    x0 += k0; x1 += k1 + 3u;
    HR(17) HR(29) HR(16) HR(24)
    x0 += k1; x1 += k2 + 4u;
    HR(13) HR(15) HR(26) HR(6)
    x0 += k2; x1 += k0 + 5u;
#undef HR
    *o0 = x0; *o1 = x1;
}

extern "C" void kernel_launch(void* const* d_in, const int* in_sizes, int n_in,
                              void* d_out, int out_size)
{
    const float* x   = (const float*)d_in[0];
    float*       out = (float*)d_out;
    const int n  = in_sizes[0];
    const int n4 = n >> 2;
    const int n8 = n4 >> 1;          // float4-pair groups; covers 8*n8 elements
    const int covered = n8 << 3;

    // folded key: fold_in(key(42), 0) = threefry((0,42), (0,0))
    uint32_t fk0, fk1;
    host_threefry(0u, 42u, 0u, 0u, &fk0, &fk1);
    uint32_t fk2  = fk0 ^ fk1 ^ 0x1BD11BDAu;
    uint32_t k2p1 = fk2 + 1u;
    uint32_t k0p2 = fk0 + 2u;
    uint32_t k1p3 = fk1 + 3u;
    uint32_t k2p4 = fk2 + 4u;
    uint32_t k0p5 = fk0 + 5u;

    if (n8 > 0) {
        // exactly one wave: SMs x max-resident-blocks (robust to regcount/SM count)
        int dev = 0, sms = 148, bpsm = 8;
        cudaGetDevice(&dev);
        cudaDeviceGetAttribute(&sms, cudaDevAttrMultiProcessorCount, dev);
        cudaOccupancyMaxActiveBlocksPerMultiprocessor(&bpsm, dq_main, 256, 0);
        if (bpsm < 1) bpsm = 1;
        long long want = (long long)sms * bpsm;
        long long need = ((long long)n8 + 255) / 256;
        unsigned blocks = (unsigned)(want < need ? want : need);
        if (blocks < 1u) blocks = 1u;

        dq_main<<<blocks, 256>>>((const float4*)x, (float4*)out, (unsigned)n8,
                                 fk0, fk1, fk2, k2p1, k0p2, k1p3, k2p4, k0p5);
    }
    if (covered < n) {
        dq_tail<<<1, 1>>>(x, out, covered, n,
                          fk0, fk1, fk2, k2p1, k0p2, k1p3, k2p4, k0p5);
    }

    dq_config<<<1, 1>>>((float)n);

    dq_fixup<<<2048, 256>>>(x, out, n,
                            fk0, fk1, fk2, k2p1, k0p2, k1p3, k2p4, k0p5);
}

// round 17
// speedup vs baseline: 1.0131x; 1.0067x over previous
#include <cuda_runtime.h>
#include <stdint.h>

// ======================= device globals (scratch; no allocs) =======================
// Statically zero-initialized; dq_config resets counters after reading them, so
// every graph replay starts from the same state (no init kernel needed).
__device__ unsigned int g_over_cnt  = 0u;
__device__ unsigned int g_under_cnt = 0u;
__device__ float4       g_qparams;   // {sigma, 1/sigma, t_min, t_max}
__device__ int          g_fix;       // 1 if speculation (sigma=0.125) was wrong

// ======================= threefry2x32 (20 rounds, Random123/JAX) ===================
// Best-measured config (R10): one mul-rotate round, IADD3-fused key injections.
__device__ __forceinline__ uint32_t rotl_mul(uint32_t x, uint32_t pow)
{
    uint32_t lo, hi;
    asm("mul.lo.u32 %0, %1, %2;" : "=r"(lo) : "r"(x), "r"(pow));
    asm("mul.hi.u32 %0, %1, %2;" : "=r"(hi) : "r"(x), "r"(pow));
    return lo | hi;
}

// Counter = (0, ctr); returns o0 ^ o1 (JAX partitionable 32-bit bits).
__device__ __forceinline__ uint32_t tf_bits32(
    uint32_t x1,               // caller passes ctr + k1
    uint32_t k0, uint32_t k1, uint32_t k2,
    uint32_t k2p1, uint32_t k0p2, uint32_t k1p3, uint32_t k2p4, uint32_t k0p5)
{
#define TF_R(r)  { x0 += x1; x1 = __funnelshift_l(x1, x1, (r)); x1 ^= x0; }
#define TF_RM(r) { x0 += x1; x1 = rotl_mul(x1, 1u << (r)) ^ x0; }
    // rounds 1-4 (x0 starts at k0)
    uint32_t x0 = k0 + x1;
    x1 = __funnelshift_l(x1, x1, 13) ^ x0;
    TF_R(15) TF_RM(26) TF_R(6)            // round 3: mul-rotate
    // inject (k1, k2+1), rounds 5-8
    x1 += k2p1; x0 = x0 + x1 + k1;
    x1 = __funnelshift_l(x1, x1, 17) ^ x0;
    TF_R(29) TF_R(16) TF_R(24)
    // inject (k2, k0+2), rounds 9-12
    x1 += k0p2; x0 = x0 + x1 + k2;
    x1 = __funnelshift_l(x1, x1, 13) ^ x0;
    TF_R(15) TF_R(26) TF_R(6)
    // inject (k0, k1+3), rounds 13-16
    x1 += k1p3; x0 = x0 + x1 + k0;
    x1 = __funnelshift_l(x1, x1, 17) ^ x0;
    TF_R(29) TF_R(16) TF_R(24)
    // inject (k1, k2+4), rounds 17-20
    x1 += k2p4; x0 = x0 + x1 + k1;
    x1 = __funnelshift_l(x1, x1, 13) ^ x0;
    TF_R(15) TF_R(26) TF_R(6)
    // final injection (k2, k0+5) folded into the output xor's operands
    return (x0 + k2) ^ (x1 + k0p5);
#undef TF_R
#undef TF_RM
}

// JAX uniform in [0,1): (float)(bits>>9) * 2^-23, bit-exact vs bitcast-or-sub-1.
__device__ __forceinline__ float tf_uniform(uint32_t bits)
{
    return (float)__umulhi(bits, 1u << 23) * 0x1p-23f;
}

// floor + clamp-to-[-128,127] in one conversion op, then scale.
// Exact: clip(floor(t)*s, -128s, 127s) == clamp(floor(t),-128,127)*s for s=2^-k.
__device__ __forceinline__ float dq_floor_sat_scale(float t, float sigma)
{
    int s8;
    asm("cvt.rmi.sat.s8.f32 %0, %1;" : "=r"(s8) : "f"(t));
    float f;
    asm("cvt.rn.f32.s8 %0, %1;" : "=f"(f) : "r"(s8));
    return f * sigma;
}

// Exact shifted-abs overflow/underflow tests (sigma0 = 0.25):
//   over : v>31.75  || v<-32  <=> |v+0.125 | > 31.875
//   under: v>15.875 || v<-16  <=> |v+0.0625| > 15.9375
__device__ __forceinline__ void dq_count_exact(float v, unsigned& over, unsigned& under)
{
    over  += (unsigned)(fabsf(v + 0.125f)  > 31.875f);
    under += (unsigned)(fabsf(v + 0.0625f) > 15.9375f);
}

// ======================= kernels ===================================================

// Persistent fused kernel. KEY CHANGE vs R14: __launch_bounds__(256, 4) relaxes
// the register cap from 32 to 64 so ptxas can keep all 8 hash chains live
// concurrently (true 8-way ILP) instead of serializing them in a 32-reg budget.
// 4 blocks/SM = 8 warps/SMSP; R14 showed occupancy 59% vs 94% is time-neutral,
// so trading occupancy for ILP is the right direction if ILP is the limiter.
__global__ void __launch_bounds__(256, 4) dq_main(
    const float4* __restrict__ x, float4* __restrict__ out, unsigned n8,
    uint32_t k0, uint32_t k1, uint32_t k2,
    uint32_t k2p1, uint32_t k0p2, uint32_t k1p3, uint32_t k2p4, uint32_t k0p5)
{
    const unsigned tid0   = blockIdx.x * blockDim.x + threadIdx.x;
    const unsigned stride = gridDim.x * blockDim.x;

    float m_acc = 0.0f;

    for (unsigned i = tid0; i < n8; i += stride) {
        unsigned j = i + n8;
        float4 va = x[i];
        float4 vb = x[j];
        uint32_t ca = i * 4u + k1;      // ctr + k1
        uint32_t cb = j * 4u + k1;

        uint32_t b0 = tf_bits32(ca + 0u, k0, k1, k2, k2p1, k0p2, k1p3, k2p4, k0p5);
        uint32_t b1 = tf_bits32(ca + 1u, k0, k1, k2, k2p1, k0p2, k1p3, k2p4, k0p5);
        uint32_t b2 = tf_bits32(ca + 2u, k0, k1, k2, k2p1, k0p2, k1p3, k2p4, k0p5);
        uint32_t b3 = tf_bits32(ca + 3u, k0, k1, k2, k2p1, k0p2, k1p3, k2p4, k0p5);
        uint32_t b4 = tf_bits32(cb + 0u, k0, k1, k2, k2p1, k0p2, k1p3, k2p4, k0p5);
        uint32_t b5 = tf_bits32(cb + 1u, k0, k1, k2, k2p1, k0p2, k1p3, k2p4, k0p5);
        uint32_t b6 = tf_bits32(cb + 2u, k0, k1, k2, k2p1, k0p2, k1p3, k2p4, k0p5);
        uint32_t b7 = tf_bits32(cb + 3u, k0, k1, k2, k2p1, k0p2, k1p3, k2p4, k0p5);

        float t0 = fmaf(va.x, 8.0f, tf_uniform(b0));
        float t1 = fmaf(va.y, 8.0f, tf_uniform(b1));
        float t2 = fmaf(va.z, 8.0f, tf_uniform(b2));
        float t3 = fmaf(va.w, 8.0f, tf_uniform(b3));
        float t4 = fmaf(vb.x, 8.0f, tf_uniform(b4));
        float t5 = fmaf(vb.y, 8.0f, tf_uniform(b5));
        float t6 = fmaf(vb.z, 8.0f, tf_uniform(b6));
        float t7 = fmaf(vb.w, 8.0f, tf_uniform(b7));

        float4 qa, qb;
        qa.x = dq_floor_sat_scale(t0, 0.125f);
        qa.y = dq_floor_sat_scale(t1, 0.125f);
        qa.z = dq_floor_sat_scale(t2, 0.125f);
        qa.w = dq_floor_sat_scale(t3, 0.125f);
        qb.x = dq_floor_sat_scale(t4, 0.125f);
        qb.y = dq_floor_sat_scale(t5, 0.125f);
        qb.z = dq_floor_sat_scale(t6, 0.125f);
        qb.w = dq_floor_sat_scale(t7, 0.125f);
        out[i] = qa;
        out[j] = qb;

        // running conservative max over all elements this thread touched
        float m = fmaxf(fmaxf(fmaxf(fabsf(t0), fabsf(t1)), fmaxf(fabsf(t2), fabsf(t3))),
                        fmaxf(fmaxf(fabsf(t4), fabsf(t5)), fmaxf(fabsf(t6), fabsf(t7))));
        m_acc = fmaxf(m_acc, m);
    }

    // single warp-converged vote per thread (all threads exit the loop)
    if (__any_sync(0xffffffffu, m_acc > 127.0f)) {
        unsigned over = 0u, under = 0u;
        for (unsigned i = tid0; i < n8; i += stride) {
            float4 va = x[i];
            float4 vb = x[i + n8];
            dq_count_exact(va.x, over, under);
            dq_count_exact(va.y, over, under);
            dq_count_exact(va.z, over, under);
            dq_count_exact(va.w, over, under);
            dq_count_exact(vb.x, over, under);
            dq_count_exact(vb.y, over, under);
            dq_count_exact(vb.z, over, under);
            dq_count_exact(vb.w, over, under);
        }
#pragma unroll
        for (int o = 16; o > 0; o >>= 1) {
            over  += __shfl_down_sync(0xffffffffu, over,  o);
            under += __shfl_down_sync(0xffffffffu, under, o);
        }
        if ((threadIdx.x & 31) == 0 && (over | under)) {
            atomicAdd(&g_over_cnt,  over);
            atomicAdd(&g_under_cnt, under);
        }
    }
}

// Scalar tail: exact count + speculative quant for elements [start, n).
__global__ void dq_tail(const float* __restrict__ x, float* __restrict__ out,
                        int start, int n,
                        uint32_t k0, uint32_t k1, uint32_t k2,
                        uint32_t k2p1, uint32_t k0p2, uint32_t k1p3,
                        uint32_t k2p4, uint32_t k0p5)
{
    unsigned over = 0u, under = 0u;
    for (int i = start; i < n; i++) {
        float v = x[i];
        dq_count_exact(v, over, under);
        uint32_t b = tf_bits32((uint32_t)i + k1, k0, k1, k2,
                               k2p1, k0p2, k1p3, k2p4, k0p5);
        float t = fmaf(v, 8.0f, tf_uniform(b));
        out[i] = dq_floor_sat_scale(t, 0.125f);
    }
    if (over)  atomicAdd(&g_over_cnt,  over);
    if (under) atomicAdd(&g_under_cnt, under);
}

// Decision (mirrors reference float32 math) + counter reset for replay determinism.
__global__ void dq_config(float nf)
{
    float overf  = (float)g_over_cnt  / nf;
    float underf = (float)g_under_cnt / nf;
    float sigma, inv;
    if (overf > 0.01f)        { sigma = 0.5f;   inv = 2.0f; }
    else if (underf < 0.01f)  { sigma = 0.125f; inv = 8.0f; }
    else                      { sigma = 0.25f;  inv = 4.0f; }
    g_qparams = make_float4(sigma, inv, -sigma * 128.0f, sigma * 127.0f);
    g_fix = (sigma != 0.125f) ? 1 : 0;
    g_over_cnt  = 0u;     // self-clean: next replay starts from zero
    g_under_cnt = 0u;
}

// Conditional fixup: re-quantize with the chosen sigma iff speculation was wrong.
// Smaller grid (512 blocks): the common-case early-exit cost drops; the rare
// correction path is memory-latency-bound and grid-stride covers n regardless.
__global__ void __launch_bounds__(256) dq_fixup(
    const float* __restrict__ x, float* __restrict__ out, int n,
    uint32_t k0, uint32_t k1, uint32_t k2,
    uint32_t k2p1, uint32_t k0p2, uint32_t k1p3, uint32_t k2p4, uint32_t k0p5)
{
    if (!g_fix) return;
    float4 p = g_qparams;
    const float sigma = p.x, inv = p.y;
    for (int i = blockIdx.x * blockDim.x + threadIdx.x; i < n;
         i += gridDim.x * blockDim.x) {
        uint32_t b = tf_bits32((uint32_t)i + k1, k0, k1, k2,
                               k2p1, k0p2, k1p3, k2p4, k0p5);
        float t = fmaf(x[i], inv, tf_uniform(b));
        out[i] = dq_floor_sat_scale(t, sigma);
    }
}

// ======================= host side =================================================
static inline uint32_t h_rotl(uint32_t v, int r) { return (v << r) | (v >> (32 - r)); }

static void host_threefry(uint32_t k0, uint32_t k1, uint32_t x0, uint32_t x1,
                          uint32_t* o0, uint32_t* o1)
{
    uint32_t k2 = k0 ^ k1 ^ 0x1BD11BDAu;
    x0 += k0; x1 += k1;
#define HR(r) { x0 += x1; x1 = h_rotl(x1, (r)); x1 ^= x0; }
    HR(13) HR(15) HR(26) HR(6)
    x0 += k1; x1 += k2 + 1u;
    HR(17) HR(29) HR(16) HR(24)
    x0 += k2; x1 += k0 + 2u;
    HR(13) HR(15) HR(26) HR(6)
    x0 += k0; x1 += k1 + 3u;
    HR(17) HR(29) HR(16) HR(24)
    x0 += k1; x1 += k2 + 4u;
    HR(13) HR(15) HR(26) HR(6)
    x0 += k2; x1 += k0 + 5u;
#undef HR
    *o0 = x0; *o1 = x1;
}

extern "C" void kernel_launch(void* const* d_in, const int* in_sizes, int n_in,
                              void* d_out, int out_size)
{
    const float* x   = (const float*)d_in[0];
    float*       out = (float*)d_out;
    const int n  = in_sizes[0];
    const int n4 = n >> 2;
    const int n8 = n4 >> 1;          // float4-pair groups; covers 8*n8 elements
    const int covered = n8 << 3;

    // folded key: fold_in(key(42), 0) = threefry((0,42), (0,0))
    uint32_t fk0, fk1;
    host_threefry(0u, 42u, 0u, 0u, &fk0, &fk1);
    uint32_t fk2  = fk0 ^ fk1 ^ 0x1BD11BDAu;
    uint32_t k2p1 = fk2 + 1u;
    uint32_t k0p2 = fk0 + 2u;
    uint32_t k1p3 = fk1 + 3u;
    uint32_t k2p4 = fk2 + 4u;
    uint32_t k0p5 = fk0 + 5u;

    if (n8 > 0) {
        // one wave at the (now register-relaxed) occupancy
        int dev = 0, sms = 148, bpsm = 4;
        cudaGetDevice(&dev);
        cudaDeviceGetAttribute(&sms, cudaDevAttrMultiProcessorCount, dev);
        cudaOccupancyMaxActiveBlocksPerMultiprocessor(&bpsm, dq_main, 256, 0);
        if (bpsm < 1) bpsm = 1;
        long long want = (long long)sms * bpsm;
        long long need = ((long long)n8 + 255) / 256;
        unsigned blocks = (unsigned)(want < need ? want : need);
        if (blocks < 1u) blocks = 1u;

        dq_main<<<blocks, 256>>>((const float4*)x, (float4*)out, (unsigned)n8,
                                 fk0, fk1, fk2, k2p1, k0p2, k1p3, k2p4, k0p5);
    }
    if (covered < n) {
        dq_tail<<<1, 1>>>(x, out, covered, n,
                          fk0, fk1, fk2, k2p1, k0p2, k1p3, k2p4, k0p5);
    }

    dq_config<<<1, 1>>>((float)n);

    dq_fixup<<<512, 256>>>(x, out, n,
                           fk0, fk1, fk2, k2p1, k0p2, k1p3, k2p4, k0p5);
}